// round 11
// baseline (speedup 1.0000x reference)
#include <cuda_runtime.h>
#include <cuda_bf16.h>
#include <cstdint>

// ---------------------------------------------------------------------------
// Problem constants
// ---------------------------------------------------------------------------
#define BB 16
#define TT 1024
#define FIN 128
#define HH 256
#define G4 1024            // 4*H
#define MM (BB*TT)         // 16384

typedef unsigned long long ull;

// ---------------------------------------------------------------------------
// Scratch (static device arrays; no dynamic allocation allowed)
// ---------------------------------------------------------------------------
__device__ float g_xg [MM * G4];      // gate preactivations (reused layer0/1)
__device__ float g_h1 [MM * HH];      // layer0 hidden sequence
__device__ float g_h2 [MM * HH];      // layer1 hidden sequence (lstm_out)
__device__ float g_Q  [MM * HH];
__device__ float g_K  [MM * HH];
__device__ float g_V  [MM * HH];
__device__ float g_S  [BB * TT * TT]; // attention scores / probs
__device__ float g_att[MM * HH];
__device__ float g_dump[4 * BB * HH]; // fallback sink for h_n/c_n

// ---------------------------------------------------------------------------
// Helpers
// ---------------------------------------------------------------------------
__device__ __forceinline__ uint32_t smem_u32(const void* p) {
    return (uint32_t)__cvta_generic_to_shared(p);
}
__device__ __forceinline__ void st_cluster_f32(uint32_t saddr, int dst_rank, float v) {
    uint32_t r;
    asm volatile("mapa.shared::cluster.u32 %0, %1, %2;" : "=r"(r) : "r"(saddr), "r"(dst_rank));
    asm volatile("st.shared::cluster.f32 [%0], %1;" :: "r"(r), "f"(v) : "memory");
}
// release-store a flag (step counter) into peer dst_rank's smem.
// Cumulative RELEASE: orders all writes that happened-before (incl. other
// lanes' DSMEM h stores chained through __syncwarp). NO separate fence —
// cluster fences cost an L1D flush each (R9->R10 finding: -313us/layer).
__device__ __forceinline__ void st_cluster_flag_release(uint32_t saddr, int dst_rank, int val) {
    asm volatile(
        "{\n\t"
        ".reg .b32 ra;\n\t"
        "mapa.shared::cluster.u32 ra, %0, %1;\n\t"
        "st.release.cluster.shared::cluster.b32 [ra], %2;\n\t"
        "}"
        :: "r"(saddr), "r"(dst_rank), "r"(val) : "memory");
}
// acquire-load a local flag (cluster scope) — proven R6/R10 spin path.
__device__ __forceinline__ int ld_acquire_cluster(uint32_t saddr) {
    int v;
    asm volatile("ld.acquire.cluster.shared::cta.b32 %0, [%1];" : "=r"(v) : "r"(saddr) : "memory");
    return v;
}
__device__ __forceinline__ void cluster_sync_all() {
    asm volatile("barrier.cluster.arrive.aligned;" ::: "memory");
    asm volatile("barrier.cluster.wait.aligned;" ::: "memory");
}
// MUFU-based activations (ex2 + rcp approx paths; ~1-2 ulp)
__device__ __forceinline__ float fast_sigmoid(float x) {
    return __fdividef(1.f, 1.f + __expf(-x));
}
__device__ __forceinline__ float fast_tanh(float x) {
    float e = __expf(2.f * x);         // inf for large x is fine: 1 - 2/inf = 1
    return 1.f - __fdividef(2.f, e + 1.f);
}

// packed fp32x2 fma: d.lo += a.lo*b.lo ; d.hi += a.hi*b.hi
__device__ __forceinline__ void ffma2(ull& d, ull a, ull b) {
    asm("fma.rn.f32x2 %0, %1, %2, %0;" : "+l"(d) : "l"(a), "l"(b));
}
__device__ __forceinline__ void unpack2(ull v, float& lo, float& hi) {
    asm("mov.b64 {%0, %1}, %2;" : "=f"(lo), "=f"(hi) : "l"(v));
}

// ---------------------------------------------------------------------------
// Persistent LSTM recurrence kernel — WARP-AUTONOMOUS (R7 design, corrected:
// NO per-step cluster fences [R10 lesson], proven 32-bit acquire polls).
// 16 clusters (batches) x 8 CTAs x 8 warps. No intra-CTA sync in the loop.
// Warp w of CTA r owns hidden dims [32r+4w, 32r+4w+4) for ALL 4 gates:
// 16 Whh rows register-resident (64 ull/lane = 128 regs).
// Lane l: gate g = l>>3, k-chunk kc = l&7 (k-pairs 2kc+16m).
// Per step, per warp (fully independent):
//   GEMV (64 FFMA2) -> 3-stage 8-lane xor reduce -> +xg (kc==0 lane)
//   -> 16-shfl gather (lane j<4 gets gate q from lane 8q)
//   -> lanes 0-3: activation chains, h DSMEM store to all 8 ranks
//   -> __syncwarp -> lanes 0-7: release flag (slot rank*8+w) to all ranks
//   -> acquire-spin until all 64 flags of the write buffer == t.
// WAR safety: warp's flag(t) is posted after ITS reads of h_all[rb(t)];
// a writer touches that buffer again (t+2... actually t+1 writes wb only)
// only after observing ALL 64 flags(t) — every reader certified.
// Monotone counters -> no ABA. All warps post before spinning -> progress.
// ---------------------------------------------------------------------------
__global__ void __cluster_dims__(8, 1, 1) __launch_bounds__(256, 1)
lstm_rec_kernel(const float* __restrict__ xg, const float* __restrict__ Whh,
                float* __restrict__ hseq, float* __restrict__ hn, float* __restrict__ cn)
{
    __shared__ float h_all[2][HH];
    __shared__ int   flags[2][64];

    const int tid   = threadIdx.x;
    const int rank  = blockIdx.x & 7;
    const int batch = blockIdx.x >> 3;
    const int w     = tid >> 5;    // warp id 0..7
    const int lane  = tid & 31;
    const int g     = lane >> 3;   // gate 0..3 (i,f,g,o row blocks)
    const int kc    = lane & 7;    // k chunk 0..7
    const int hidb  = 32 * rank + 4 * w;   // global hid base of this warp

    // ---- load 16 Whh rows (gate g x 4 hids) as f32x2 k-pairs ----
    ull w2[4][16];
    #pragma unroll
    for (int j = 0; j < 4; j++) {
        const int row = 256 * g + hidb + j;
        const float* wr = Whh + (long)row * HH;
        #pragma unroll
        for (int m = 0; m < 16; m++) {
            float2 wp = *(const float2*)(wr + 2 * kc + 16 * m);
            ull v;
            asm("mov.b64 %0, {%1, %2};" : "=l"(v) : "f"(wp.x), "f"(wp.y));
            w2[j][m] = v;
        }
    }

    h_all[0][tid] = 0.f;
    if (tid < 128) flags[tid >> 6][tid & 63] = -1;

    float c_state = 0.f;                 // live in lanes 0..3 (hid hidb+lane)
    const uint32_t fbase = smem_u32(&flags[0][0]);
    // this warp's flag slot byte offset (same location in every CTA's smem)
    const uint32_t fslot = fbase + ((rank * 8 + w) << 2);
    // spin poll addresses: lane polls flags[wb][lane] and flags[wb][32+lane]
    const uint32_t fspin = fbase + (lane << 2);
    // h store local-view addresses (lanes 0..3 store hid hidb+lane)
    uint32_t haddr[2];
    haddr[0] = smem_u32(&h_all[0][hidb + lane]);
    haddr[1] = smem_u32(&h_all[1][hidb + lane]);

    __syncthreads();
    cluster_sync_all();   // flags init + h0 visible cluster-wide

    const long xg_base = (long)batch * TT * G4;
    const int  xg_col  = 256 * g + hidb;   // float4 col base (kc==0 lane of group)

    // prefetch xg for t=0
    float4 xgv = make_float4(0.f, 0.f, 0.f, 0.f);
    if (kc == 0) xgv = *(const float4*)(xg + xg_base + xg_col);

    for (int t = 0; t < TT; t++) {
        const int rb = t & 1;
        const int wb = rb ^ 1;

        // ---- GEMV: 4 rows x 16 k-pairs = 64 FFMA2 ----
        ull acc2[4] = {0ull, 0ull, 0ull, 0ull};
        const float* hrow = h_all[rb];
        #pragma unroll
        for (int m = 0; m < 16; m++) {
            ull h2 = *(const ull*)(hrow + 2 * kc + 16 * m);
            ffma2(acc2[0], w2[0][m], h2);
            ffma2(acc2[1], w2[1][m], h2);
            ffma2(acc2[2], w2[2][m], h2);
            ffma2(acc2[3], w2[3][m], h2);
        }
        float sums[4];
        #pragma unroll
        for (int j = 0; j < 4; j++) {
            float lo, hi;
            unpack2(acc2[j], lo, hi);
            sums[j] = lo + hi;
        }
        // reduce over the 8 lanes of this gate group (xor 4,2,1)
        #pragma unroll
        for (int off = 4; off >= 1; off >>= 1) {
            sums[0] += __shfl_xor_sync(0xffffffffu, sums[0], off);
            sums[1] += __shfl_xor_sync(0xffffffffu, sums[1], off);
            sums[2] += __shfl_xor_sync(0xffffffffu, sums[2], off);
            sums[3] += __shfl_xor_sync(0xffffffffu, sums[3], off);
        }
        // add xg preactivation on the kc==0 lane of each gate group
        if (kc == 0) {
            sums[0] += xgv.x; sums[1] += xgv.y; sums[2] += xgv.z; sums[3] += xgv.w;
        }
        // gather: lane j (0..3) collects gate q (complete value at lane 8q)
        float gate[4];
        #pragma unroll
        for (int q = 0; q < 4; q++) {
            #pragma unroll
            for (int j = 0; j < 4; j++) {
                float v = __shfl_sync(0xffffffffu, sums[j], 8 * q);
                if (lane == j) gate[q] = v;
            }
        }

        // ---- lanes 0-3: activation chains (parallel across 4 hid dims) ----
        float h = 0.f;
        if (lane < 4) {
            float ig = fast_sigmoid(gate[0]);
            float fg = fast_sigmoid(gate[1]);
            float gt = fast_tanh(gate[2]);
            float og = fast_sigmoid(gate[3]);
            c_state = fg * c_state + ig * gt;
            h = og * fast_tanh(c_state);
            // broadcast h to all 8 CTAs' h_all[wb]
            uint32_t dst = haddr[wb];
            #pragma unroll
            for (int d = 0; d < 8; d++) st_cluster_f32(dst, d, h);
        }
        __syncwarp(0xffffffffu);       // chain lanes 0-3's h stores before releases
        if (lane < 8) {
            // cumulative release: post step counter into peer `lane`'s
            // flags[wb][rank*8+w]; orders the h stores above.
            st_cluster_flag_release(fslot + (wb << 8), lane, t);
        }
        // gmem stores off the critical path
        if (lane < 4) {
            hseq[((long)batch * TT + t) * HH + hidb + lane] = h;
            if (t == TT - 1) {
                hn[batch * HH + hidb + lane] = h;
                cn[batch * HH + hidb + lane] = c_state;
            }
        }

        // prefetch next xg row (independent; before the spin)
        if (kc == 0 && t + 1 < TT) {
            xgv = *(const float4*)(xg + xg_base + (long)(t + 1) * G4 + xg_col);
        }

        // ---- acquire spin: all 64 flags of buffer wb must equal t ----
        {
            const uint32_t fa = fspin + (wb << 8);
            int v0, v1;
            do {
                v0 = ld_acquire_cluster(fa);
                v1 = ld_acquire_cluster(fa + 128);
            } while (__any_sync(0xffffffffu, (v0 != t) | (v1 != t)));
        }
    }
}

// ---------------------------------------------------------------------------
// SGEMM (proven R2 version): C[M,N] = A[M,K] @ B^T (b_nt=1, B is [N,K]) or
// A @ B (b_nt=0, B is [K,N]) + optional bias1[n] + bias2[n] + residual[m,n].
// Batched via gridDim.z with element strides sA/sB/sC. Tiles 128x128x8,
// 256 threads, 8x8 microtiles.
// ---------------------------------------------------------------------------
__global__ __launch_bounds__(256) void sgemm_kernel(
    const float* __restrict__ A, const float* __restrict__ B, float* __restrict__ C,
    int M, int N, int K,
    long sA, long sB, long sC,
    const float* __restrict__ bias1, const float* __restrict__ bias2,
    const float* __restrict__ res,
    int b_nt)
{
    __shared__ float As[8][132];
    __shared__ float Bs[8][132];

    const int bz = blockIdx.z;
    A += (long)bz * sA;
    B += (long)bz * sB;
    C += (long)bz * sC;

    const int bm = blockIdx.y * 128;
    const int bn = blockIdx.x * 128;
    const int tid = threadIdx.x;
    const int tx = tid & 15;
    const int ty = tid >> 4;

    float acc[8][8];
    #pragma unroll
    for (int i = 0; i < 8; i++)
        #pragma unroll
        for (int j = 0; j < 8; j++) acc[i][j] = 0.f;

    const int lr  = tid >> 1;        // 0..127
    const int lc4 = (tid & 1) * 4;   // 0 or 4
    const int kb  = tid >> 5;        // 0..7   (NN B load)
    const int nb  = (tid & 31) * 4;  // 0..124

    for (int k0 = 0; k0 < K; k0 += 8) {
        float4 a4 = *(const float4*)(A + (long)(bm + lr) * K + k0 + lc4);
        As[lc4 + 0][lr] = a4.x;
        As[lc4 + 1][lr] = a4.y;
        As[lc4 + 2][lr] = a4.z;
        As[lc4 + 3][lr] = a4.w;
        if (b_nt) {
            float4 b4 = *(const float4*)(B + (long)(bn + lr) * K + k0 + lc4);
            Bs[lc4 + 0][lr] = b4.x;
            Bs[lc4 + 1][lr] = b4.y;
            Bs[lc4 + 2][lr] = b4.z;
            Bs[lc4 + 3][lr] = b4.w;
        } else {
            float4 b4 = *(const float4*)(B + (long)(k0 + kb) * N + bn + nb);
            *(float4*)&Bs[kb][nb] = b4;
        }
        __syncthreads();

        #pragma unroll
        for (int kk = 0; kk < 8; kk++) {
            float a[8], b[8];
            *(float4*)&a[0] = *(const float4*)&As[kk][ty * 4];
            *(float4*)&a[4] = *(const float4*)&As[kk][64 + ty * 4];
            *(float4*)&b[0] = *(const float4*)&Bs[kk][tx * 4];
            *(float4*)&b[4] = *(const float4*)&Bs[kk][64 + tx * 4];
            #pragma unroll
            for (int i = 0; i < 8; i++)
                #pragma unroll
                for (int j = 0; j < 8; j++)
                    acc[i][j] = fmaf(a[i], b[j], acc[i][j]);
        }
        __syncthreads();
    }

    // epilogue
    #pragma unroll
    for (int ih = 0; ih < 2; ih++) {
        #pragma unroll
        for (int i = 0; i < 4; i++) {
            int m = bm + ih * 64 + ty * 4 + i;
            #pragma unroll
            for (int jh = 0; jh < 2; jh++) {
                int n = bn + jh * 64 + tx * 4;
                float4 v;
                v.x = acc[ih * 4 + i][jh * 4 + 0];
                v.y = acc[ih * 4 + i][jh * 4 + 1];
                v.z = acc[ih * 4 + i][jh * 4 + 2];
                v.w = acc[ih * 4 + i][jh * 4 + 3];
                if (bias1) {
                    const float4 b1 = *(const float4*)(bias1 + n);
                    v.x += b1.x; v.y += b1.y; v.z += b1.z; v.w += b1.w;
                }
                if (bias2) {
                    const float4 b2 = *(const float4*)(bias2 + n);
                    v.x += b2.x; v.y += b2.y; v.z += b2.z; v.w += b2.w;
                }
                if (res) {
                    const float4 r = *(const float4*)(res + (long)m * N + n);
                    v.x += r.x; v.y += r.y; v.z += r.z; v.w += r.w;
                }
                *(float4*)(C + (long)m * N + n) = v;
            }
        }
    }
}

// ---------------------------------------------------------------------------
// Softmax with ARMA modulation. One block (256 thr) per (b,q) row of 1024.
// mod depends only on d=|q-k| and is non-trivial only for d<=3.
// ---------------------------------------------------------------------------
__global__ __launch_bounds__(256) void softmax_mod_kernel(
    float* __restrict__ S, const float* __restrict__ ar_w, const float* __restrict__ ma_w)
{
    __shared__ float red[8];
    const int row = blockIdx.x;          // b*1024 + q
    const int q = row & (TT - 1);
    float* Sr = S + (long)row * TT;

    const float m0 = ma_w[0], m1 = ma_w[1];
    const float a0 = ar_w[0], a1 = ar_w[1], a2 = ar_w[2];
    const float mod0 = __expf(m0 + m1);
    const float mod1 = __expf(a0 + m0 + m1);
    const float mod2 = __expf(a1 + m1);
    const float mod3 = __expf(a2);

    const int t = threadIdx.x;
    float v[4];
    float mx = -1e30f;
    #pragma unroll
    for (int i = 0; i < 4; i++) {
        int k = t + 256 * i;
        float s = Sr[k] * 0.0625f;   // 1/sqrt(256)
        int d = ::abs(q - k);
        float md = (d > 3) ? 1.f : (d == 0 ? mod0 : (d == 1 ? mod1 : (d == 2 ? mod2 : mod3)));
        v[i] = s * md;
        mx = fmaxf(mx, v[i]);
    }
    #pragma unroll
    for (int off = 16; off; off >>= 1) mx = fmaxf(mx, __shfl_xor_sync(~0u, mx, off));
    if ((t & 31) == 0) red[t >> 5] = mx;
    __syncthreads();
    mx = red[0];
    #pragma unroll
    for (int w = 1; w < 8; w++) mx = fmaxf(mx, red[w]);

    float sum = 0.f;
    #pragma unroll
    for (int i = 0; i < 4; i++) { v[i] = __expf(v[i] - mx); sum += v[i]; }
    #pragma unroll
    for (int off = 16; off; off >>= 1) sum += __shfl_xor_sync(~0u, sum, off);
    __syncthreads();
    if ((t & 31) == 0) red[t >> 5] = sum;
    __syncthreads();
    sum = 0.f;
    #pragma unroll
    for (int w = 0; w < 8; w++) sum += red[w];
    const float inv = 1.f / sum;
    #pragma unroll
    for (int i = 0; i < 4; i++) Sr[t + 256 * i] = v[i] * inv;
}

// ---------------------------------------------------------------------------
// Launch
// ---------------------------------------------------------------------------
extern "C" void kernel_launch(void* const* d_in, const int* in_sizes, int n_in,
                              void* d_out, int out_size)
{
    const float* x    = (const float*)d_in[0];
    const float* Wih0 = (const float*)d_in[1];
    const float* Whh0 = (const float*)d_in[2];
    const float* bih0 = (const float*)d_in[3];
    const float* bhh0 = (const float*)d_in[4];
    const float* Wih1 = (const float*)d_in[5];
    const float* Whh1 = (const float*)d_in[6];
    const float* bih1 = (const float*)d_in[7];
    const float* bhh1 = (const float*)d_in[8];
    const float* ar_w = (const float*)d_in[9];
    const float* ma_w = (const float*)d_in[10];
    const float* Wq   = (const float*)d_in[11];
    const float* bq   = (const float*)d_in[12];
    const float* Wk   = (const float*)d_in[13];
    const float* bk   = (const float*)d_in[14];
    const float* Wv   = (const float*)d_in[15];
    const float* bv   = (const float*)d_in[16];
    const float* Wo   = (const float*)d_in[17];
    const float* bo   = (const float*)d_in[18];

    float* out = (float*)d_out;

    float *xg, *h1, *h2, *Q, *K, *V, *S, *att, *dump;
    cudaGetSymbolAddress((void**)&xg,  g_xg);
    cudaGetSymbolAddress((void**)&h1,  g_h1);
    cudaGetSymbolAddress((void**)&h2,  g_h2);
    cudaGetSymbolAddress((void**)&Q,   g_Q);
    cudaGetSymbolAddress((void**)&K,   g_K);
    cudaGetSymbolAddress((void**)&V,   g_V);
    cudaGetSymbolAddress((void**)&S,   g_S);
    cudaGetSymbolAddress((void**)&att, g_att);
    cudaGetSymbolAddress((void**)&dump, g_dump);

    // h_n / c_n destinations (appended after `out` if the buffer has room)
    const int OUT_ELEMS = MM * HH;            // 4194304
    float* hn_base;
    float* cn_base;
    if (out_size >= OUT_ELEMS + 4 * BB * HH) {
        hn_base = out + OUT_ELEMS;
        cn_base = out + OUT_ELEMS + 2 * BB * HH;
    } else {
        hn_base = dump;
        cn_base = dump + BB * HH;
    }

    const dim3 g_xg_grid(G4 / 128, MM / 128, 1);
    const dim3 g_qkv(HH / 128, MM / 128, 1);
    const dim3 g_sc(TT / 128, TT / 128, BB);
    const dim3 g_av(HH / 128, TT / 128, BB);

    // layer 0
    sgemm_kernel<<<g_xg_grid, 256>>>(x, Wih0, xg, MM, G4, FIN, 0, 0, 0, bih0, bhh0, nullptr, 1);
    lstm_rec_kernel<<<128, 256>>>(xg, Whh0, h1, hn_base, cn_base);
    // layer 1
    sgemm_kernel<<<g_xg_grid, 256>>>(h1, Wih1, xg, MM, G4, HH, 0, 0, 0, bih1, bhh1, nullptr, 1);
    lstm_rec_kernel<<<128, 256>>>(xg, Whh1, h2, hn_base + BB * HH, cn_base + BB * HH);
    // Q, K, V
    sgemm_kernel<<<g_qkv, 256>>>(h2, Wq, Q, MM, HH, HH, 0, 0, 0, bq, nullptr, nullptr, 1);
    sgemm_kernel<<<g_qkv, 256>>>(h2, Wk, K, MM, HH, HH, 0, 0, 0, bk, nullptr, nullptr, 1);
    sgemm_kernel<<<g_qkv, 256>>>(h2, Wv, V, MM, HH, HH, 0, 0, 0, bv, nullptr, nullptr, 1);
    // scores = Q @ K^T (batched)
    sgemm_kernel<<<g_sc, 256>>>(Q, K, S, TT, TT, HH,
                                (long)TT * HH, (long)TT * HH, (long)TT * TT,
                                nullptr, nullptr, nullptr, 1);
    // softmax(scores/sqrt(H) * mod)
    softmax_mod_kernel<<<BB * TT, 256>>>(S, ar_w, ma_w);
    // attended = attn @ V (batched, NN)
    sgemm_kernel<<<g_av, 256>>>(S, V, att, TT, HH, TT,
                                (long)TT * TT, (long)TT * HH, (long)TT * HH,
                                nullptr, nullptr, nullptr, 0);
    // out = attended @ Wo^T + bo + lstm_out
    sgemm_kernel<<<g_qkv, 256>>>(att, Wo, out, MM, HH, HH, 0, 0, 0, bo, nullptr, h2, 1);
}

// round 13
// speedup vs baseline: 1.2131x; 1.2131x over previous
#include <cuda_runtime.h>
#include <cuda_bf16.h>
#include <cstdint>

// ---------------------------------------------------------------------------
// Problem constants
// ---------------------------------------------------------------------------
#define BB 16
#define TT 1024
#define FIN 128
#define HH 256
#define G4 1024            // 4*H
#define MM (BB*TT)         // 16384

typedef unsigned long long ull;

// ---------------------------------------------------------------------------
// Scratch (static device arrays; no dynamic allocation allowed)
// ---------------------------------------------------------------------------
__device__ float g_xg [MM * G4];      // gate preactivations (reused layer0/1)
__device__ float g_h1 [MM * HH];      // layer0 hidden sequence
__device__ float g_h2 [MM * HH];      // layer1 hidden sequence (lstm_out)
__device__ float g_Q  [MM * HH];
__device__ float g_K  [MM * HH];
__device__ float g_V  [MM * HH];
__device__ float g_S  [BB * TT * TT]; // attention scores / probs
__device__ float g_att[MM * HH];
__device__ float g_dump[4 * BB * HH]; // fallback sink for h_n/c_n

// ---------------------------------------------------------------------------
// Helpers
// ---------------------------------------------------------------------------
__device__ __forceinline__ uint32_t smem_u32(const void* p) {
    return (uint32_t)__cvta_generic_to_shared(p);
}
__device__ __forceinline__ void st_cluster_f32(uint32_t saddr, int dst_rank, float v) {
    uint32_t r;
    asm volatile("mapa.shared::cluster.u32 %0, %1, %2;" : "=r"(r) : "r"(saddr), "r"(dst_rank));
    asm volatile("st.shared::cluster.f32 [%0], %1;" :: "r"(r), "f"(v) : "memory");
}
// release-store a flag (step counter) into peer dst_rank's smem.
// Cumulative RELEASE: orders all program-prior writes (incl. the DSMEM h
// stores). NO separate cluster fence — fences cost an L1D flush each
// (R9->R10 finding: -313us/layer).
__device__ __forceinline__ void st_cluster_flag_release(uint32_t saddr, int dst_rank, int val) {
    asm volatile(
        "{\n\t"
        ".reg .b32 ra;\n\t"
        "mapa.shared::cluster.u32 ra, %0, %1;\n\t"
        "st.release.cluster.shared::cluster.b32 [ra], %2;\n\t"
        "}"
        :: "r"(saddr), "r"(dst_rank), "r"(val) : "memory");
}
// acquire-load a local flag (cluster scope) — proven R6/R10 spin path.
__device__ __forceinline__ int ld_acquire_cluster(uint32_t saddr) {
    int v;
    asm volatile("ld.acquire.cluster.shared::cta.b32 %0, [%1];" : "=r"(v) : "r"(saddr) : "memory");
    return v;
}
__device__ __forceinline__ void cluster_sync_all() {
    asm volatile("barrier.cluster.arrive.aligned;" ::: "memory");
    asm volatile("barrier.cluster.wait.aligned;" ::: "memory");
}
// HW tanh (single MUFU op, sm_75+). abs err ~1e-4 — fine vs 1e-3 threshold.
__device__ __forceinline__ float tanh_approx(float x) {
    float r;
    asm("tanh.approx.f32 %0, %1;" : "=f"(r) : "f"(x));
    return r;
}
// sigmoid via tanh: s(x) = 0.5*tanh(x/2) + 0.5  (1 MUFU + 1 MUL + 1 FMA)
__device__ __forceinline__ float fast_sigmoid(float x) {
    return fmaf(0.5f, tanh_approx(0.5f * x), 0.5f);
}
__device__ __forceinline__ float fast_tanh(float x) {
    return tanh_approx(x);
}

// packed fp32x2 fma: d.lo += a.lo*b.lo ; d.hi += a.hi*b.hi
__device__ __forceinline__ void ffma2(ull& d, ull a, ull b) {
    asm("fma.rn.f32x2 %0, %1, %2, %0;" : "+l"(d) : "l"(a), "l"(b));
}
__device__ __forceinline__ ull dup2(float x) {
    ull r;
    asm("mov.b64 %0, {%1, %1};" : "=l"(r) : "f"(x));
    return r;
}
__device__ __forceinline__ void unpack2(ull v, float& lo, float& hi) {
    asm("mov.b64 {%0, %1}, %2;" : "=f"(lo), "=f"(hi) : "l"(v));
}

// ---------------------------------------------------------------------------
// Persistent LSTM recurrence kernel — R10 structure EXACTLY (best measured:
// 2145us/layer), with only the activation math swapped to HW tanh.approx
// (serial warp0 stage: ~10 MUFU -> 5 MUFU, shorter dependency chain).
// 16 clusters (batches) x 8 CTAs. Each CTA owns 32 hidden dims; Whh slice
// (128x256 fp32 = 128KB) register-resident as f32x2 pairs. Thread t:
// u=t>>3 -> outputs o=4u..4u+3, kc=t&7 -> k-pairs {2kc+16j,+1}.
// Per step: all warps GEMV (64 FFMA2) + 8-lane shfl reduce -> gates_s ->
// __syncthreads -> warp0: activations, 8x DSMEM h store, __syncwarp,
// lanes 0-7 post release flags into all 8 CTAs -> all warps acquire-spin
// on the 8 local flags == t.
// Hazards (as R6/R10): a CTA's flag for step t is posted after its
// __syncthreads (all reads of h_all[rb(t)] and gates_s writes done); a
// peer rewrites that buffer only in step t+1 after observing all 8 step-t
// flags. Monotone counters -> no ABA.
// ---------------------------------------------------------------------------
__global__ void __cluster_dims__(8, 1, 1) __launch_bounds__(256, 1)
lstm_rec_kernel(const float* __restrict__ xg, const float* __restrict__ Whh,
                float* __restrict__ hseq, float* __restrict__ hn, float* __restrict__ cn)
{
    __shared__ float h_all[2][HH];
    __shared__ float gates_s[128];
    __shared__ int   flags[2][8];

    const int tid   = threadIdx.x;
    const int rank  = blockIdx.x & 7;
    const int batch = blockIdx.x >> 3;
    const int u     = tid >> 3;   // 0..31 : output group (4 outputs, same gate)
    const int kc    = tid & 7;    // 0..7  : k-pair subset
    const int o0    = 4 * u;      // local output base

    // ---- load Whh slice into registers as f32x2 k-pairs ----
    ull w2[4][16];
    #pragma unroll
    for (int oo = 0; oo < 4; oo++) {
        const int o   = o0 + oo;
        const int row = ((o >> 5) << 8) + 32 * rank + (o & 31);
        const float* wr = Whh + (long)row * HH;
        #pragma unroll
        for (int j = 0; j < 16; j++) {
            float2 wp = *(const float2*)(wr + 2 * kc + 16 * j);
            ull v;
            asm("mov.b64 %0, {%1, %2};" : "=l"(v) : "f"(wp.x), "f"(wp.y));
            w2[oo][j] = v;
        }
    }

    h_all[0][tid] = 0.f;
    if (tid < 16) flags[tid >> 3][tid & 7] = -1;

    float c_state = 0.f;
    uint32_t haddr[2] = {0, 0};
    if (tid < 32) {
        haddr[0] = smem_u32(&h_all[0][32 * rank + tid]);
        haddr[1] = smem_u32(&h_all[1][32 * rank + tid]);
    }
    const uint32_t fbase = smem_u32(&flags[0][0]);
    // spin address for this thread (lane-cyclic over the 8 flags)
    const uint32_t fspin0 = fbase + ((tid & 7) << 2);
    // flag address (local view) this CTA posts into peers: flags[wb][rank]
    const uint32_t fpost0 = fbase + (rank << 2);

    __syncthreads();
    cluster_sync_all();   // flags init + h0 visible cluster-wide

    const long xg_base = (long)batch * TT * G4;
    const int  xg_col  = ((o0 >> 5) << 8) + 32 * rank + (o0 & 31); // 4 consecutive cols

    // prefetch xg for t=0
    float4 xgv = make_float4(0.f, 0.f, 0.f, 0.f);
    if (kc == 0) xgv = *(const float4*)(xg + xg_base + xg_col);

    for (int t = 0; t < TT; t++) {
        const int rb = t & 1;
        const int wb = rb ^ 1;

        // GEMV over h_all[rb] : 64 FFMA2
        ull acc2[4] = {0ull, 0ull, 0ull, 0ull};
        const float* hrow = h_all[rb];
        #pragma unroll
        for (int j = 0; j < 16; j++) {
            ull h2 = *(const ull*)(hrow + 2 * kc + 16 * j);
            ffma2(acc2[0], w2[0][j], h2);
            ffma2(acc2[1], w2[1][j], h2);
            ffma2(acc2[2], w2[2][j], h2);
            ffma2(acc2[3], w2[3][j], h2);
        }
        float acc[4];
        #pragma unroll
        for (int g = 0; g < 4; g++) {
            float lo, hi;
            unpack2(acc2[g], lo, hi);
            acc[g] = lo + hi;
        }
        #pragma unroll
        for (int off = 4; off >= 1; off >>= 1) {
            acc[0] += __shfl_xor_sync(0xffffffffu, acc[0], off);
            acc[1] += __shfl_xor_sync(0xffffffffu, acc[1], off);
            acc[2] += __shfl_xor_sync(0xffffffffu, acc[2], off);
            acc[3] += __shfl_xor_sync(0xffffffffu, acc[3], off);
        }
        if (kc == 0) {
            *(float4*)&gates_s[o0] =
                make_float4(acc[0] + xgv.x, acc[1] + xgv.y, acc[2] + xgv.z, acc[3] + xgv.w);
        }
        __syncthreads();   // all warps done reading h_all[rb]; gates_s ready

        if (tid < 32) {    // warp 0 = writer warp
            const int hid = tid;
            float gi = gates_s[hid];
            float gf = gates_s[32 + hid];
            float gg = gates_s[64 + hid];
            float go = gates_s[96 + hid];
            float ig = fast_sigmoid(gi);
            float fg = fast_sigmoid(gf);
            float gt = fast_tanh(gg);
            float og = fast_sigmoid(go);
            c_state = fg * c_state + ig * gt;
            float h = og * fast_tanh(c_state);
            uint32_t dst = haddr[wb];
            #pragma unroll
            for (int d = 0; d < 8; d++) st_cluster_f32(dst, d, h);
            __syncwarp(0xffffffffu);     // all lanes' DSMEM h stores issued
            if (tid < 8) {
                // post step counter into peer tid's flags[wb][rank]
                st_cluster_flag_release(fpost0 + (wb << 5), tid, t);
            }
            // gmem stores off the cluster critical path
            hseq[((long)batch * TT + t) * HH + 32 * rank + hid] = h;
            if (t == TT - 1) {
                hn[batch * HH + 32 * rank + hid] = h;
                cn[batch * HH + 32 * rank + hid] = c_state;
            }
        }

        // prefetch next xg row (independent; issued before the spin)
        if (kc == 0 && t + 1 < TT) {
            xgv = *(const float4*)(xg + xg_base + (long)(t + 1) * G4 + xg_col);
        }

        // acquire-poll spin: wait until all 8 CTAs posted step t for buffer wb
        {
            const uint32_t fa = fspin0 + (wb << 5);
            int v;
            do {
                v = ld_acquire_cluster(fa);
            } while (__any_sync(0xffffffffu, v != t));
        }
    }
}

// ---------------------------------------------------------------------------
// SGEMM: R2-proven structure (loaders, BK=8, barriers, epilogue mapping all
// IDENTICAL) with ONLY the 8x8 microkernel swapped to packed f32x2 FMA:
// 64 FFMA -> 32 FFMA2 + 8 dups per kk (issue slots 68 -> ~46).
// C[M,N] = A[M,K] @ B^T (b_nt=1) or A @ B (b_nt=0), + bias1/bias2/residual.
// ---------------------------------------------------------------------------
__global__ __launch_bounds__(256) void sgemm_kernel(
    const float* __restrict__ A, const float* __restrict__ B, float* __restrict__ C,
    int M, int N, int K,
    long sA, long sB, long sC,
    const float* __restrict__ bias1, const float* __restrict__ bias2,
    const float* __restrict__ res,
    int b_nt)
{
    __shared__ float As[8][132];
    __shared__ float Bs[8][132];

    const int bz = blockIdx.z;
    A += (long)bz * sA;
    B += (long)bz * sB;
    C += (long)bz * sC;

    const int bm = blockIdx.y * 128;
    const int bn = blockIdx.x * 128;
    const int tid = threadIdx.x;
    const int tx = tid & 15;
    const int ty = tid >> 4;

    ull acc2[8][4];
    #pragma unroll
    for (int i = 0; i < 8; i++)
        #pragma unroll
        for (int j = 0; j < 4; j++) acc2[i][j] = 0ull;

    const int lr  = tid >> 1;        // 0..127
    const int lc4 = (tid & 1) * 4;   // 0 or 4
    const int kb  = tid >> 5;        // 0..7   (NN B load)
    const int nb  = (tid & 31) * 4;  // 0..124

    for (int k0 = 0; k0 < K; k0 += 8) {
        float4 a4 = *(const float4*)(A + (long)(bm + lr) * K + k0 + lc4);
        As[lc4 + 0][lr] = a4.x;
        As[lc4 + 1][lr] = a4.y;
        As[lc4 + 2][lr] = a4.z;
        As[lc4 + 3][lr] = a4.w;
        if (b_nt) {
            float4 b4 = *(const float4*)(B + (long)(bn + lr) * K + k0 + lc4);
            Bs[lc4 + 0][lr] = b4.x;
            Bs[lc4 + 1][lr] = b4.y;
            Bs[lc4 + 2][lr] = b4.z;
            Bs[lc4 + 3][lr] = b4.w;
        } else {
            float4 b4 = *(const float4*)(B + (long)(k0 + kb) * N + bn + nb);
            *(float4*)&Bs[kb][nb] = b4;
        }
        __syncthreads();

        #pragma unroll
        for (int kk = 0; kk < 8; kk++) {
            float a[8];
            *(float4*)&a[0] = *(const float4*)&As[kk][ty * 4];
            *(float4*)&a[4] = *(const float4*)&As[kk][64 + ty * 4];
            ull b2[4];
            b2[0] = *(const ull*)&Bs[kk][4 * tx];
            b2[1] = *(const ull*)&Bs[kk][4 * tx + 2];
            b2[2] = *(const ull*)&Bs[kk][64 + 4 * tx];
            b2[3] = *(const ull*)&Bs[kk][64 + 4 * tx + 2];
            #pragma unroll
            for (int i = 0; i < 8; i++) {
                ull a2 = dup2(a[i]);
                ffma2(acc2[i][0], a2, b2[0]);
                ffma2(acc2[i][1], a2, b2[1]);
                ffma2(acc2[i][2], a2, b2[2]);
                ffma2(acc2[i][3], a2, b2[3]);
            }
        }
        __syncthreads();
    }

    // epilogue (same mapping as R2/R3: acc2[i][2jh] = cols {0,1}, [2jh+1] = {2,3})
    #pragma unroll
    for (int ih = 0; ih < 2; ih++) {
        #pragma unroll
        for (int i = 0; i < 4; i++) {
            int m = bm + ih * 64 + ty * 4 + i;
            #pragma unroll
            for (int jh = 0; jh < 2; jh++) {
                int n = bn + jh * 64 + tx * 4;
                float4 v;
                unpack2(acc2[ih * 4 + i][2 * jh],     v.x, v.y);
                unpack2(acc2[ih * 4 + i][2 * jh + 1], v.z, v.w);
                if (bias1) {
                    const float4 b1 = *(const float4*)(bias1 + n);
                    v.x += b1.x; v.y += b1.y; v.z += b1.z; v.w += b1.w;
                }
                if (bias2) {
                    const float4 b2v = *(const float4*)(bias2 + n);
                    v.x += b2v.x; v.y += b2v.y; v.z += b2v.z; v.w += b2v.w;
                }
                if (res) {
                    const float4 r = *(const float4*)(res + (long)m * N + n);
                    v.x += r.x; v.y += r.y; v.z += r.z; v.w += r.w;
                }
                *(float4*)(C + (long)m * N + n) = v;
            }
        }
    }
}

// ---------------------------------------------------------------------------
// Softmax with ARMA modulation. One block (256 thr) per (b,q) row of 1024.
// mod depends only on d=|q-k| and is non-trivial only for d<=3.
// ---------------------------------------------------------------------------
__global__ __launch_bounds__(256) void softmax_mod_kernel(
    float* __restrict__ S, const float* __restrict__ ar_w, const float* __restrict__ ma_w)
{
    __shared__ float red[8];
    const int row = blockIdx.x;          // b*1024 + q
    const int q = row & (TT - 1);
    float* Sr = S + (long)row * TT;

    const float m0 = ma_w[0], m1 = ma_w[1];
    const float a0 = ar_w[0], a1 = ar_w[1], a2 = ar_w[2];
    const float mod0 = __expf(m0 + m1);
    const float mod1 = __expf(a0 + m0 + m1);
    const float mod2 = __expf(a1 + m1);
    const float mod3 = __expf(a2);

    const int t = threadIdx.x;
    float v[4];
    float mx = -1e30f;
    #pragma unroll
    for (int i = 0; i < 4; i++) {
        int k = t + 256 * i;
        float s = Sr[k] * 0.0625f;   // 1/sqrt(256)
        int d = ::abs(q - k);
        float md = (d > 3) ? 1.f : (d == 0 ? mod0 : (d == 1 ? mod1 : (d == 2 ? mod2 : mod3)));
        v[i] = s * md;
        mx = fmaxf(mx, v[i]);
    }
    #pragma unroll
    for (int off = 16; off; off >>= 1) mx = fmaxf(mx, __shfl_xor_sync(~0u, mx, off));
    if ((t & 31) == 0) red[t >> 5] = mx;
    __syncthreads();
    mx = red[0];
    #pragma unroll
    for (int w = 1; w < 8; w++) mx = fmaxf(mx, red[w]);

    float sum = 0.f;
    #pragma unroll
    for (int i = 0; i < 4; i++) { v[i] = __expf(v[i] - mx); sum += v[i]; }
    #pragma unroll
    for (int off = 16; off; off >>= 1) sum += __shfl_xor_sync(~0u, sum, off);
    __syncthreads();
    if ((t & 31) == 0) red[t >> 5] = sum;
    __syncthreads();
    sum = 0.f;
    #pragma unroll
    for (int w = 0; w < 8; w++) sum += red[w];
    const float inv = 1.f / sum;
    #pragma unroll
    for (int i = 0; i < 4; i++) Sr[t + 256 * i] = v[i] * inv;
}

// ---------------------------------------------------------------------------
// Launch
// ---------------------------------------------------------------------------
extern "C" void kernel_launch(void* const* d_in, const int* in_sizes, int n_in,
                              void* d_out, int out_size)
{
    const float* x    = (const float*)d_in[0];
    const float* Wih0 = (const float*)d_in[1];
    const float* Whh0 = (const float*)d_in[2];
    const float* bih0 = (const float*)d_in[3];
    const float* bhh0 = (const float*)d_in[4];
    const float* Wih1 = (const float*)d_in[5];
    const float* Whh1 = (const float*)d_in[6];
    const float* bih1 = (const float*)d_in[7];
    const float* bhh1 = (const float*)d_in[8];
    const float* ar_w = (const float*)d_in[9];
    const float* ma_w = (const float*)d_in[10];
    const float* Wq   = (const float*)d_in[11];
    const float* bq   = (const float*)d_in[12];
    const float* Wk   = (const float*)d_in[13];
    const float* bk   = (const float*)d_in[14];
    const float* Wv   = (const float*)d_in[15];
    const float* bv   = (const float*)d_in[16];
    const float* Wo   = (const float*)d_in[17];
    const float* bo   = (const float*)d_in[18];

    float* out = (float*)d_out;

    float *xg, *h1, *h2, *Q, *K, *V, *S, *att, *dump;
    cudaGetSymbolAddress((void**)&xg,  g_xg);
    cudaGetSymbolAddress((void**)&h1,  g_h1);
    cudaGetSymbolAddress((void**)&h2,  g_h2);
    cudaGetSymbolAddress((void**)&Q,   g_Q);
    cudaGetSymbolAddress((void**)&K,   g_K);
    cudaGetSymbolAddress((void**)&V,   g_V);
    cudaGetSymbolAddress((void**)&S,   g_S);
    cudaGetSymbolAddress((void**)&att, g_att);
    cudaGetSymbolAddress((void**)&dump, g_dump);

    // h_n / c_n destinations (appended after `out` if the buffer has room)
    const int OUT_ELEMS = MM * HH;            // 4194304
    float* hn_base;
    float* cn_base;
    if (out_size >= OUT_ELEMS + 4 * BB * HH) {
        hn_base = out + OUT_ELEMS;
        cn_base = out + OUT_ELEMS + 2 * BB * HH;
    } else {
        hn_base = dump;
        cn_base = dump + BB * HH;
    }

    const dim3 g_xg_grid(G4 / 128, MM / 128, 1);
    const dim3 g_qkv(HH / 128, MM / 128, 1);
    const dim3 g_sc(TT / 128, TT / 128, BB);
    const dim3 g_av(HH / 128, TT / 128, BB);

    // layer 0
    sgemm_kernel<<<g_xg_grid, 256>>>(x, Wih0, xg, MM, G4, FIN, 0, 0, 0, bih0, bhh0, nullptr, 1);
    lstm_rec_kernel<<<128, 256>>>(xg, Whh0, h1, hn_base, cn_base);
    // layer 1
    sgemm_kernel<<<g_xg_grid, 256>>>(h1, Wih1, xg, MM, G4, HH, 0, 0, 0, bih1, bhh1, nullptr, 1);
    lstm_rec_kernel<<<128, 256>>>(xg, Whh1, h2, hn_base + BB * HH, cn_base + BB * HH);
    // Q, K, V
    sgemm_kernel<<<g_qkv, 256>>>(h2, Wq, Q, MM, HH, HH, 0, 0, 0, bq, nullptr, nullptr, 1);
    sgemm_kernel<<<g_qkv, 256>>>(h2, Wk, K, MM, HH, HH, 0, 0, 0, bk, nullptr, nullptr, 1);
    sgemm_kernel<<<g_qkv, 256>>>(h2, Wv, V, MM, HH, HH, 0, 0, 0, bv, nullptr, nullptr, 1);
    // scores = Q @ K^T (batched)
    sgemm_kernel<<<g_sc, 256>>>(Q, K, S, TT, TT, HH,
                                (long)TT * HH, (long)TT * HH, (long)TT * TT,
                                nullptr, nullptr, nullptr, 1);
    // softmax(scores/sqrt(H) * mod)
    softmax_mod_kernel<<<BB * TT, 256>>>(S, ar_w, ma_w);
    // attended = attn @ V (batched, NN)
    sgemm_kernel<<<g_av, 256>>>(S, V, att, TT, HH, TT,
                                (long)TT * TT, (long)TT * HH, (long)TT * HH,
                                nullptr, nullptr, nullptr, 0);
    // out = attended @ Wo^T + bo + lstm_out
    sgemm_kernel<<<g_qkv, 256>>>(att, Wo, out, MM, HH, HH, 0, 0, 0, bo, nullptr, h2, 1);
}

// round 15
// speedup vs baseline: 1.2483x; 1.0290x over previous
#include <cuda_runtime.h>
#include <cuda_bf16.h>
#include <cstdint>

// ---------------------------------------------------------------------------
// Problem constants
// ---------------------------------------------------------------------------
#define BB 16
#define TT 1024
#define FIN 128
#define HH 256
#define G4 1024            // 4*H
#define MM (BB*TT)         // 16384

typedef unsigned long long ull;

// ---------------------------------------------------------------------------
// Scratch (static device arrays; no dynamic allocation allowed)
// ---------------------------------------------------------------------------
__device__ float g_xg [MM * G4];      // gate preactivations (reused layer0/1)
__device__ float g_h1 [MM * HH];      // layer0 hidden sequence
__device__ float g_h2 [MM * HH];      // layer1 hidden sequence (lstm_out)
__device__ float g_Q  [MM * HH];
__device__ float g_K  [MM * HH];
__device__ float g_V  [MM * HH];
__device__ float g_S  [BB * TT * TT]; // attention scores / probs
__device__ float g_att[MM * HH];
__device__ float g_dump[4 * BB * HH]; // fallback sink for h_n/c_n

// ---------------------------------------------------------------------------
// Helpers
// ---------------------------------------------------------------------------
__device__ __forceinline__ uint32_t smem_u32(const void* p) {
    return (uint32_t)__cvta_generic_to_shared(p);
}
__device__ __forceinline__ void st_cluster_f32(uint32_t saddr, int dst_rank, float v) {
    uint32_t r;
    asm volatile("mapa.shared::cluster.u32 %0, %1, %2;" : "=r"(r) : "r"(saddr), "r"(dst_rank));
    asm volatile("st.shared::cluster.f32 [%0], %1;" :: "r"(r), "f"(v) : "memory");
}
// release-store a flag (step counter) into peer dst_rank's smem.
// Cumulative RELEASE: orders all program-prior writes (incl. the DSMEM h
// stores). NO separate cluster fence — fences cost an L1D flush each
// (R9->R10 finding: -313us/layer).
__device__ __forceinline__ void st_cluster_flag_release(uint32_t saddr, int dst_rank, int val) {
    asm volatile(
        "{\n\t"
        ".reg .b32 ra;\n\t"
        "mapa.shared::cluster.u32 ra, %0, %1;\n\t"
        "st.release.cluster.shared::cluster.b32 [ra], %2;\n\t"
        "}"
        :: "r"(saddr), "r"(dst_rank), "r"(val) : "memory");
}
__device__ __forceinline__ void cluster_sync_all() {
    asm volatile("barrier.cluster.arrive.aligned;" ::: "memory");
    asm volatile("barrier.cluster.wait.aligned;" ::: "memory");
}
// HW tanh (single MUFU op). abs err ~1e-4 — proven R13: rel_err 5e-6.
__device__ __forceinline__ float tanh_approx(float x) {
    float r;
    asm("tanh.approx.f32 %0, %1;" : "=f"(r) : "f"(x));
    return r;
}
__device__ __forceinline__ float fast_sigmoid(float x) {
    return fmaf(0.5f, tanh_approx(0.5f * x), 0.5f);
}
__device__ __forceinline__ float fast_tanh(float x) {
    return tanh_approx(x);
}

// packed fp32x2 fma: d.lo += a.lo*b.lo ; d.hi += a.hi*b.hi
__device__ __forceinline__ void ffma2(ull& d, ull a, ull b) {
    asm("fma.rn.f32x2 %0, %1, %2, %0;" : "+l"(d) : "l"(a), "l"(b));
}
__device__ __forceinline__ ull dup2(float x) {
    ull r;
    asm("mov.b64 %0, {%1, %1};" : "=l"(r) : "f"(x));
    return r;
}
__device__ __forceinline__ void unpack2(ull v, float& lo, float& hi) {
    asm("mov.b64 {%0, %1}, %2;" : "=f"(lo), "=f"(hi) : "l"(v));
}

// ---------------------------------------------------------------------------
// Persistent LSTM recurrence kernel — R13 structure EXACTLY (best measured:
// 2027us/layer) with ONE change in the spin: poll with CHEAP volatile LDS
// (~30cyc local) instead of per-poll ld.acquire.cluster (cluster-scope sync
// machinery, suspected ~100-150cyc/poll), then a SINGLE ld.acquire.cluster
// after exit. The acquire reads the released flag value -> synchronizes-with
// the writer's st.release.cluster -> orders subsequent h_all reads. Same
// memory-model guarantees as R13, minus the per-poll toll. No fences.
// 16 clusters (batches) x 8 CTAs. Whh register-resident as f32x2 pairs.
// Per step: all warps GEMV (64 FFMA2) + 8-lane shfl reduce -> gates_s ->
// __syncthreads -> warp0: tanh.approx activations, 8x DSMEM h store,
// __syncwarp, lanes 0-7 post release flags into all 8 CTAs -> all warps
// volatile-spin on the 8 local flags == t, then one acquire load.
// Hazards (as R10/R13): flag(t) posted after __syncthreads (all reads of
// h_all[rb(t)] done); buffer rewritten only after observing all 8 step-t
// flags. Monotone counters -> no ABA.
// ---------------------------------------------------------------------------
__global__ void __cluster_dims__(8, 1, 1) __launch_bounds__(256, 1)
lstm_rec_kernel(const float* __restrict__ xg, const float* __restrict__ Whh,
                float* __restrict__ hseq, float* __restrict__ hn, float* __restrict__ cn)
{
    __shared__ float h_all[2][HH];
    __shared__ float gates_s[128];
    __shared__ int   flags[2][8];

    const int tid   = threadIdx.x;
    const int rank  = blockIdx.x & 7;
    const int batch = blockIdx.x >> 3;
    const int u     = tid >> 3;   // 0..31 : output group (4 outputs, same gate)
    const int kc    = tid & 7;    // 0..7  : k-pair subset
    const int o0    = 4 * u;      // local output base

    // ---- load Whh slice into registers as f32x2 k-pairs ----
    ull w2[4][16];
    #pragma unroll
    for (int oo = 0; oo < 4; oo++) {
        const int o   = o0 + oo;
        const int row = ((o >> 5) << 8) + 32 * rank + (o & 31);
        const float* wr = Whh + (long)row * HH;
        #pragma unroll
        for (int j = 0; j < 16; j++) {
            float2 wp = *(const float2*)(wr + 2 * kc + 16 * j);
            ull v;
            asm("mov.b64 %0, {%1, %2};" : "=l"(v) : "f"(wp.x), "f"(wp.y));
            w2[oo][j] = v;
        }
    }

    h_all[0][tid] = 0.f;
    if (tid < 16) flags[tid >> 3][tid & 7] = -1;

    float c_state = 0.f;
    uint32_t haddr[2] = {0, 0};
    if (tid < 32) {
        haddr[0] = smem_u32(&h_all[0][32 * rank + tid]);
        haddr[1] = smem_u32(&h_all[1][32 * rank + tid]);
    }
    const uint32_t fbase = smem_u32(&flags[0][0]);
    // spin address for this thread (lane-cyclic over the 8 flags)
    const uint32_t fspin0 = fbase + ((tid & 7) << 2);
    // flag address (local view) this CTA posts into peers: flags[wb][rank]
    const uint32_t fpost0 = fbase + (rank << 2);

    __syncthreads();
    cluster_sync_all();   // flags init + h0 visible cluster-wide

    const long xg_base = (long)batch * TT * G4;
    const int  xg_col  = ((o0 >> 5) << 8) + 32 * rank + (o0 & 31); // 4 consecutive cols

    // prefetch xg for t=0
    float4 xgv = make_float4(0.f, 0.f, 0.f, 0.f);
    if (kc == 0) xgv = *(const float4*)(xg + xg_base + xg_col);

    for (int t = 0; t < TT; t++) {
        const int rb = t & 1;
        const int wb = rb ^ 1;

        // GEMV over h_all[rb] : 64 FFMA2
        ull acc2[4] = {0ull, 0ull, 0ull, 0ull};
        const float* hrow = h_all[rb];
        #pragma unroll
        for (int j = 0; j < 16; j++) {
            ull h2 = *(const ull*)(hrow + 2 * kc + 16 * j);
            ffma2(acc2[0], w2[0][j], h2);
            ffma2(acc2[1], w2[1][j], h2);
            ffma2(acc2[2], w2[2][j], h2);
            ffma2(acc2[3], w2[3][j], h2);
        }
        float acc[4];
        #pragma unroll
        for (int g = 0; g < 4; g++) {
            float lo, hi;
            unpack2(acc2[g], lo, hi);
            acc[g] = lo + hi;
        }
        #pragma unroll
        for (int off = 4; off >= 1; off >>= 1) {
            acc[0] += __shfl_xor_sync(0xffffffffu, acc[0], off);
            acc[1] += __shfl_xor_sync(0xffffffffu, acc[1], off);
            acc[2] += __shfl_xor_sync(0xffffffffu, acc[2], off);
            acc[3] += __shfl_xor_sync(0xffffffffu, acc[3], off);
        }
        if (kc == 0) {
            *(float4*)&gates_s[o0] =
                make_float4(acc[0] + xgv.x, acc[1] + xgv.y, acc[2] + xgv.z, acc[3] + xgv.w);
        }
        __syncthreads();   // all warps done reading h_all[rb]; gates_s ready

        if (tid < 32) {    // warp 0 = writer warp
            const int hid = tid;
            float gi = gates_s[hid];
            float gf = gates_s[32 + hid];
            float gg = gates_s[64 + hid];
            float go = gates_s[96 + hid];
            float ig = fast_sigmoid(gi);
            float fg = fast_sigmoid(gf);
            float gt = fast_tanh(gg);
            float og = fast_sigmoid(go);
            c_state = fg * c_state + ig * gt;
            float h = og * fast_tanh(c_state);
            uint32_t dst = haddr[wb];
            #pragma unroll
            for (int d = 0; d < 8; d++) st_cluster_f32(dst, d, h);
            __syncwarp(0xffffffffu);     // all lanes' DSMEM h stores issued
            if (tid < 8) {
                // post step counter into peer tid's flags[wb][rank]
                st_cluster_flag_release(fpost0 + (wb << 5), tid, t);
            }
            // gmem stores off the cluster critical path
            hseq[((long)batch * TT + t) * HH + 32 * rank + hid] = h;
            if (t == TT - 1) {
                hn[batch * HH + 32 * rank + hid] = h;
                cn[batch * HH + 32 * rank + hid] = c_state;
            }
        }

        // prefetch next xg row (independent; issued before the spin)
        if (kc == 0 && t + 1 < TT) {
            xgv = *(const float4*)(xg + xg_base + (long)(t + 1) * G4 + xg_col);
        }

        // cheap volatile spin, then ONE acquire load for ordering
        {
            const uint32_t fa = fspin0 + (wb << 5);
            int v;
            do {
                asm volatile("ld.volatile.shared.b32 %0, [%1];" : "=r"(v) : "r"(fa) : "memory");
            } while (__any_sync(0xffffffffu, v != t));
            // reads the released value -> synchronizes-with the release store
            asm volatile("ld.acquire.cluster.shared::cta.b32 %0, [%1];" : "=r"(v) : "r"(fa) : "memory");
        }
    }
}

// ---------------------------------------------------------------------------
// SGEMM: R2 structure + f32x2 microkernel (R13-proven).
// C[M,N] = A[M,K] @ B^T (b_nt=1) or A @ B (b_nt=0), + bias1/bias2/residual.
// ---------------------------------------------------------------------------
__global__ __launch_bounds__(256) void sgemm_kernel(
    const float* __restrict__ A, const float* __restrict__ B, float* __restrict__ C,
    int M, int N, int K,
    long sA, long sB, long sC,
    const float* __restrict__ bias1, const float* __restrict__ bias2,
    const float* __restrict__ res,
    int b_nt)
{
    __shared__ float As[8][132];
    __shared__ float Bs[8][132];

    const int bz = blockIdx.z;
    A += (long)bz * sA;
    B += (long)bz * sB;
    C += (long)bz * sC;

    const int bm = blockIdx.y * 128;
    const int bn = blockIdx.x * 128;
    const int tid = threadIdx.x;
    const int tx = tid & 15;
    const int ty = tid >> 4;

    ull acc2[8][4];
    #pragma unroll
    for (int i = 0; i < 8; i++)
        #pragma unroll
        for (int j = 0; j < 4; j++) acc2[i][j] = 0ull;

    const int lr  = tid >> 1;        // 0..127
    const int lc4 = (tid & 1) * 4;   // 0 or 4
    const int kb  = tid >> 5;        // 0..7   (NN B load)
    const int nb  = (tid & 31) * 4;  // 0..124

    for (int k0 = 0; k0 < K; k0 += 8) {
        float4 a4 = *(const float4*)(A + (long)(bm + lr) * K + k0 + lc4);
        As[lc4 + 0][lr] = a4.x;
        As[lc4 + 1][lr] = a4.y;
        As[lc4 + 2][lr] = a4.z;
        As[lc4 + 3][lr] = a4.w;
        if (b_nt) {
            float4 b4 = *(const float4*)(B + (long)(bn + lr) * K + k0 + lc4);
            Bs[lc4 + 0][lr] = b4.x;
            Bs[lc4 + 1][lr] = b4.y;
            Bs[lc4 + 2][lr] = b4.z;
            Bs[lc4 + 3][lr] = b4.w;
        } else {
            float4 b4 = *(const float4*)(B + (long)(k0 + kb) * N + bn + nb);
            *(float4*)&Bs[kb][nb] = b4;
        }
        __syncthreads();

        #pragma unroll
        for (int kk = 0; kk < 8; kk++) {
            float a[8];
            *(float4*)&a[0] = *(const float4*)&As[kk][ty * 4];
            *(float4*)&a[4] = *(const float4*)&As[kk][64 + ty * 4];
            ull b2[4];
            b2[0] = *(const ull*)&Bs[kk][4 * tx];
            b2[1] = *(const ull*)&Bs[kk][4 * tx + 2];
            b2[2] = *(const ull*)&Bs[kk][64 + 4 * tx];
            b2[3] = *(const ull*)&Bs[kk][64 + 4 * tx + 2];
            #pragma unroll
            for (int i = 0; i < 8; i++) {
                ull a2 = dup2(a[i]);
                ffma2(acc2[i][0], a2, b2[0]);
                ffma2(acc2[i][1], a2, b2[1]);
                ffma2(acc2[i][2], a2, b2[2]);
                ffma2(acc2[i][3], a2, b2[3]);
            }
        }
        __syncthreads();
    }

    // epilogue
    #pragma unroll
    for (int ih = 0; ih < 2; ih++) {
        #pragma unroll
        for (int i = 0; i < 4; i++) {
            int m = bm + ih * 64 + ty * 4 + i;
            #pragma unroll
            for (int jh = 0; jh < 2; jh++) {
                int n = bn + jh * 64 + tx * 4;
                float4 v;
                unpack2(acc2[ih * 4 + i][2 * jh],     v.x, v.y);
                unpack2(acc2[ih * 4 + i][2 * jh + 1], v.z, v.w);
                if (bias1) {
                    const float4 b1 = *(const float4*)(bias1 + n);
                    v.x += b1.x; v.y += b1.y; v.z += b1.z; v.w += b1.w;
                }
                if (bias2) {
                    const float4 b2v = *(const float4*)(bias2 + n);
                    v.x += b2v.x; v.y += b2v.y; v.z += b2v.z; v.w += b2v.w;
                }
                if (res) {
                    const float4 r = *(const float4*)(res + (long)m * N + n);
                    v.x += r.x; v.y += r.y; v.z += r.z; v.w += r.w;
                }
                *(float4*)(C + (long)m * N + n) = v;
            }
        }
    }
}

// ---------------------------------------------------------------------------
// Softmax with ARMA modulation. One block (256 thr) per (b,q) row of 1024.
// mod depends only on d=|q-k| and is non-trivial only for d<=3.
// ---------------------------------------------------------------------------
__global__ __launch_bounds__(256) void softmax_mod_kernel(
    float* __restrict__ S, const float* __restrict__ ar_w, const float* __restrict__ ma_w)
{
    __shared__ float red[8];
    const int row = blockIdx.x;          // b*1024 + q
    const int q = row & (TT - 1);
    float* Sr = S + (long)row * TT;

    const float m0 = ma_w[0], m1 = ma_w[1];
    const float a0 = ar_w[0], a1 = ar_w[1], a2 = ar_w[2];
    const float mod0 = __expf(m0 + m1);
    const float mod1 = __expf(a0 + m0 + m1);
    const float mod2 = __expf(a1 + m1);
    const float mod3 = __expf(a2);

    const int t = threadIdx.x;
    float v[4];
    float mx = -1e30f;
    #pragma unroll
    for (int i = 0; i < 4; i++) {
        int k = t + 256 * i;
        float s = Sr[k] * 0.0625f;   // 1/sqrt(256)
        int d = ::abs(q - k);
        float md = (d > 3) ? 1.f : (d == 0 ? mod0 : (d == 1 ? mod1 : (d == 2 ? mod2 : mod3)));
        v[i] = s * md;
        mx = fmaxf(mx, v[i]);
    }
    #pragma unroll
    for (int off = 16; off; off >>= 1) mx = fmaxf(mx, __shfl_xor_sync(~0u, mx, off));
    if ((t & 31) == 0) red[t >> 5] = mx;
    __syncthreads();
    mx = red[0];
    #pragma unroll
    for (int w = 1; w < 8; w++) mx = fmaxf(mx, red[w]);

    float sum = 0.f;
    #pragma unroll
    for (int i = 0; i < 4; i++) { v[i] = __expf(v[i] - mx); sum += v[i]; }
    #pragma unroll
    for (int off = 16; off; off >>= 1) sum += __shfl_xor_sync(~0u, sum, off);
    __syncthreads();
    if ((t & 31) == 0) red[t >> 5] = sum;
    __syncthreads();
    sum = 0.f;
    #pragma unroll
    for (int w = 0; w < 8; w++) sum += red[w];
    const float inv = 1.f / sum;
    #pragma unroll
    for (int i = 0; i < 4; i++) Sr[t + 256 * i] = v[i] * inv;
}

// ---------------------------------------------------------------------------
// Launch
// ---------------------------------------------------------------------------
extern "C" void kernel_launch(void* const* d_in, const int* in_sizes, int n_in,
                              void* d_out, int out_size)
{
    const float* x    = (const float*)d_in[0];
    const float* Wih0 = (const float*)d_in[1];
    const float* Whh0 = (const float*)d_in[2];
    const float* bih0 = (const float*)d_in[3];
    const float* bhh0 = (const float*)d_in[4];
    const float* Wih1 = (const float*)d_in[5];
    const float* Whh1 = (const float*)d_in[6];
    const float* bih1 = (const float*)d_in[7];
    const float* bhh1 = (const float*)d_in[8];
    const float* ar_w = (const float*)d_in[9];
    const float* ma_w = (const float*)d_in[10];
    const float* Wq   = (const float*)d_in[11];
    const float* bq   = (const float*)d_in[12];
    const float* Wk   = (const float*)d_in[13];
    const float* bk   = (const float*)d_in[14];
    const float* Wv   = (const float*)d_in[15];
    const float* bv   = (const float*)d_in[16];
    const float* Wo   = (const float*)d_in[17];
    const float* bo   = (const float*)d_in[18];

    float* out = (float*)d_out;

    float *xg, *h1, *h2, *Q, *K, *V, *S, *att, *dump;
    cudaGetSymbolAddress((void**)&xg,  g_xg);
    cudaGetSymbolAddress((void**)&h1,  g_h1);
    cudaGetSymbolAddress((void**)&h2,  g_h2);
    cudaGetSymbolAddress((void**)&Q,   g_Q);
    cudaGetSymbolAddress((void**)&K,   g_K);
    cudaGetSymbolAddress((void**)&V,   g_V);
    cudaGetSymbolAddress((void**)&S,   g_S);
    cudaGetSymbolAddress((void**)&att, g_att);
    cudaGetSymbolAddress((void**)&dump, g_dump);

    // h_n / c_n destinations (appended after `out` if the buffer has room)
    const int OUT_ELEMS = MM * HH;            // 4194304
    float* hn_base;
    float* cn_base;
    if (out_size >= OUT_ELEMS + 4 * BB * HH) {
        hn_base = out + OUT_ELEMS;
        cn_base = out + OUT_ELEMS + 2 * BB * HH;
    } else {
        hn_base = dump;
        cn_base = dump + BB * HH;
    }

    const dim3 g_xg_grid(G4 / 128, MM / 128, 1);
    const dim3 g_qkv(HH / 128, MM / 128, 1);
    const dim3 g_sc(TT / 128, TT / 128, BB);
    const dim3 g_av(HH / 128, TT / 128, BB);

    // layer 0
    sgemm_kernel<<<g_xg_grid, 256>>>(x, Wih0, xg, MM, G4, FIN, 0, 0, 0, bih0, bhh0, nullptr, 1);
    lstm_rec_kernel<<<128, 256>>>(xg, Whh0, h1, hn_base, cn_base);
    // layer 1
    sgemm_kernel<<<g_xg_grid, 256>>>(h1, Wih1, xg, MM, G4, HH, 0, 0, 0, bih1, bhh1, nullptr, 1);
    lstm_rec_kernel<<<128, 256>>>(xg, Whh1, h2, hn_base + BB * HH, cn_base + BB * HH);
    // Q, K, V
    sgemm_kernel<<<g_qkv, 256>>>(h2, Wq, Q, MM, HH, HH, 0, 0, 0, bq, nullptr, nullptr, 1);
    sgemm_kernel<<<g_qkv, 256>>>(h2, Wk, K, MM, HH, HH, 0, 0, 0, bk, nullptr, nullptr, 1);
    sgemm_kernel<<<g_qkv, 256>>>(h2, Wv, V, MM, HH, HH, 0, 0, 0, bv, nullptr, nullptr, 1);
    // scores = Q @ K^T (batched)
    sgemm_kernel<<<g_sc, 256>>>(Q, K, S, TT, TT, HH,
                                (long)TT * HH, (long)TT * HH, (long)TT * TT,
                                nullptr, nullptr, nullptr, 1);
    // softmax(scores/sqrt(H) * mod)
    softmax_mod_kernel<<<BB * TT, 256>>>(S, ar_w, ma_w);
    // attended = attn @ V (batched, NN)
    sgemm_kernel<<<g_av, 256>>>(S, V, att, TT, HH, TT,
                                (long)TT * TT, (long)TT * HH, (long)TT * HH,
                                nullptr, nullptr, nullptr, 0);
    // out = attended @ Wo^T + bo + lstm_out
    sgemm_kernel<<<g_qkv, 256>>>(att, Wo, out, MM, HH, HH, 0, 0, 0, bo, nullptr, h2, 1);
}